// round 9
// baseline (speedup 1.0000x reference)
#include <cuda_runtime.h>

#define N     2048
#define FIN   512
#define F     64
#define NT    32            // 64-row tiles per dimension
#define NTRI  528           // NT*(NT+1)/2

typedef unsigned long long u64;

// ---------------- scratch (static device allocations only) ----------------
__device__ float g_h[N * F];                 // 512 KB
__device__ float g_rowsum[N];
__device__ float g_o[N * F];                 // 512 KB accumulated output (RED)

#define ABS2MASK 0x7FFFFFFF7FFFFFFFULL

__device__ __forceinline__ u64 f2add(u64 a, u64 b) {
    u64 r; asm("add.rn.f32x2 %0, %1, %2;" : "=l"(r) : "l"(a), "l"(b)); return r;
}
__device__ __forceinline__ u64 f2fma(u64 a, u64 b, u64 c) {
    u64 r; asm("fma.rn.f32x2 %0, %1, %2, %3;" : "=l"(r) : "l"(a), "l"(b), "l"(c)); return r;
}
__device__ __forceinline__ u64 dupf(float x) {
    u64 r; unsigned u = __float_as_uint(x);
    asm("mov.b64 %0, {%1,%1};" : "=l"(r) : "r"(u)); return r;
}
__device__ __forceinline__ u64 packf(float lo, float hi) {
    u64 r; asm("mov.b64 %0, {%1,%2};" : "=l"(r) : "r"(__float_as_uint(lo)), "r"(__float_as_uint(hi)));
    return r;
}
__device__ __forceinline__ float unpack_sum(u64 v) {
    float lo, hi;
    asm("mov.b64 {%0,%1}, %2;" : "=f"(lo), "=f"(hi) : "l"(v));
    return lo + hi;
}
__device__ __forceinline__ void unpack2(u64 v, float& lo, float& hi) {
    asm("mov.b64 {%0,%1}, %2;" : "=f"(lo), "=f"(hi) : "l"(v));
}

#define FMA4(a, s, v) { (a).x += (s)*(v).x; (a).y += (s)*(v).y; (a).z += (s)*(v).z; (a).w += (s)*(v).w; }

// ---------------- K1: h = x @ W; also zeroes g_o / g_rowsum ----------------
__global__ __launch_bounds__(256) void k1_gemm_h(const float* __restrict__ x,
                                                 const float* __restrict__ W) {
    __shared__ float xs[16][FIN];   // 32 KB
    __shared__ float ws[32][F];     // 8 KB
    int tid = threadIdx.x;
    int r0 = blockIdx.x * 16;

    // zero accumulators (128 blocks x 256 threads; 1 float4 of g_o each)
    int gidx = blockIdx.x * 256 + tid;
    ((float4*)g_o)[gidx] = make_float4(0.f, 0.f, 0.f, 0.f);
    if (gidx < N) g_rowsum[gidx] = 0.0f;

    const float4* xg  = (const float4*)(x + (size_t)r0 * FIN);
    float4*       xs4 = (float4*)&xs[0][0];
#pragma unroll
    for (int u = 0; u < 8; u++) xs4[tid + u * 256] = xg[tid + u * 256];

    int tx = tid & 15;
    int ty = tid >> 4;
    float4 acc[4];
#pragma unroll
    for (int q = 0; q < 4; q++) acc[q] = make_float4(0.f, 0.f, 0.f, 0.f);

    for (int kt = 0; kt < FIN; kt += 32) {
        __syncthreads();
        const float4* wg  = (const float4*)(W + (size_t)kt * F);
        float4*       ws4 = (float4*)&ws[0][0];
        ws4[tid]       = wg[tid];
        ws4[tid + 256] = wg[tid + 256];
        __syncthreads();
#pragma unroll
        for (int k4 = 0; k4 < 8; k4++) {
            float4 xv = *(const float4*)&xs[ty][kt + k4 * 4];
            float4 w0 = ((const float4*)&ws[k4 * 4 + 0][0])[tx];
            float4 w1 = ((const float4*)&ws[k4 * 4 + 1][0])[tx];
            float4 w2 = ((const float4*)&ws[k4 * 4 + 2][0])[tx];
            float4 w3 = ((const float4*)&ws[k4 * 4 + 3][0])[tx];
            FMA4(acc[0], xv.x, w0); FMA4(acc[1], xv.y, w1);
            FMA4(acc[2], xv.z, w2); FMA4(acc[3], xv.w, w3);
        }
    }
    float4 r;
    r.x = (acc[0].x + acc[1].x) + (acc[2].x + acc[3].x);
    r.y = (acc[0].y + acc[1].y) + (acc[2].y + acc[3].y);
    r.z = (acc[0].z + acc[1].z) + (acc[2].z + acc[3].z);
    r.w = (acc[0].w + acc[1].w) + (acc[2].w + acc[3].w);
    *(float4*)&g_h[(size_t)(r0 + ty) * F + tx * 4] = r;
}

// ---------------- K23sym: symmetric fused scores + exp + both AV products --
// One block per upper-triangle tile pair (ib <= jb).
// Phase A: 64x64 E tile (exp once; adj masks per orientation) -> Pst1, Pst2.
// Phase B (MERGED): one 64-iter loop accumulating BOTH O_i (from Pst1, njs)
// and O_j (from Pst2, his) -> 8 independent fma chains for ILP. Rowsums
// accumulated as packed f32x2 on the loaded register pairs.
// Output accumulated via RED (atomicAdd) into L2-resident g_o.
#define K23S_SMEM ((4096 * 4 + 64) * 4)   // his, njs, Pst1, Pst2, a = 64.3KB

__global__ __launch_bounds__(256, 2) void k23_sym(const int* __restrict__ adj,
                                                  const float* __restrict__ a) {
    extern __shared__ float sm[];
    float* his  = sm;            // [64][64] rotated (i-tile h)
    float* njs  = sm + 4096;     // [64][64] rotated, negated (j-tile h)
    float* Pst1 = sm + 8192;     // [j][i] swizzled, mask adj[i,j]
    float* Pst2 = sm + 12288;    // [i][j] swizzled, mask adj[j,i]
    float* as_  = sm + 16384;    // [64]

    // triangular decode
    int t = blockIdx.x, ib = 0;
    while (t >= NT - ib) { t -= NT - ib; ib++; }
    int jb = ib + t;
    int gi0 = ib * 64, gj0 = jb * 64;
    bool diag = (ib == jb);

    int tid = threadIdx.x;
    int tx = tid & 15, ty = tid >> 4;
    int i0 = ty * 4, j0 = tx * 4;

    // ---- prefetch adjacency (both orientations), compress to bitmasks ----
    unsigned mij = 0, mji = 0;
#pragma unroll
    for (int k = 0; k < 4; k++) {
        int4 v = *(const int4*)&adj[(size_t)(gi0 + i0 + k) * N + gj0 + j0];
        unsigned b = (v.x > 0) | ((v.y > 0) << 1) | ((v.z > 0) << 2) | ((v.w > 0) << 3);
        mij |= b << (k * 4);     // bit (k*4+jj) = adj[gi0+i0+k][gj0+j0+jj]
    }
    if (!diag) {
#pragma unroll
        for (int jj = 0; jj < 4; jj++) {
            int4 v = *(const int4*)&adj[(size_t)(gj0 + j0 + jj) * N + gi0 + i0];
            unsigned b = (v.x > 0) | ((v.y > 0) << 1) | ((v.z > 0) << 2) | ((v.w > 0) << 3);
            mji |= b << (jj * 4);  // bit (jj*4+k) = adj[gj0+j0+jj][gi0+i0+k]
        }
    }

    // ---- stage his (rotated), njs (rotated + negated), a ----
    const float4* hgi = (const float4*)(g_h + (size_t)gi0 * F);
    const float4* hgj = (const float4*)(g_h + (size_t)gj0 * F);
#pragma unroll
    for (int u = 0; u < 4; u++) {
        int v = tid + u * 256;
        int r = v >> 4, c = v & 15;
        int cp = (c + (r >> 2)) & 15;
        *(float4*)&his[r * 64 + cp * 4] = hgi[v];
        float4 nv = hgj[v];
        nv.x = -nv.x; nv.y = -nv.y; nv.z = -nv.z; nv.w = -nv.w;
        *(float4*)&njs[r * 64 + cp * 4] = nv;
    }
    if (tid < 16) ((float4*)as_)[tid] = ((const float4*)a)[tid];
    __syncthreads();

    // ---- phase A: E tile, thread = 4i x 4j ----
    u64 accA[4][4] = {};
#pragma unroll
    for (int fc = 0; fc < 16; fc++) {
        ulonglong2 av = *(const ulonglong2*)&as_[fc * 4];
        int ci = ((fc + ty) & 15) * 4;
        int cj = ((fc + tx) & 15) * 4;
        ulonglong2 hr[4], nj[4];
#pragma unroll
        for (int k = 0; k < 4; k++) {
            hr[k] = *(const ulonglong2*)&his[(i0 + k) * 64 + ci];
            nj[k] = *(const ulonglong2*)&njs[(j0 + k) * 64 + cj];
        }
#pragma unroll
        for (int k = 0; k < 4; k++) {
#pragma unroll
            for (int jj = 0; jj < 4; jj++) {
                u64 d0 = f2add(hr[k].x, nj[jj].x) & ABS2MASK;
                accA[k][jj] = f2fma(d0, av.x, accA[k][jj]);
                u64 d1 = f2add(hr[k].y, nj[jj].y) & ABS2MASK;
                accA[k][jj] = f2fma(d1, av.y, accA[k][jj]);
            }
        }
    }

    // ---- exp once, mask twice, store Pst1 / Pst2 ----
    int swzA = (tx & 7) * 4;    // key for rows j0..j0+3  ((j>>2)&7 == tx&7)
    int swzB = (ty & 7) * 4;    // key for rows i0..i0+3
#pragma unroll
    for (int k = 0; k < 4; k++) {
        float e[4];
#pragma unroll
        for (int jj = 0; jj < 4; jj++)
            e[jj] = __expf(fmaxf(unpack_sum(accA[k][jj]), 0.f));
        int col = (i0 + k) ^ swzA;
        Pst1[(j0 + 0) * 64 + col] = (mij >> (k * 4 + 0)) & 1 ? e[0] : 0.f;
        Pst1[(j0 + 1) * 64 + col] = (mij >> (k * 4 + 1)) & 1 ? e[1] : 0.f;
        Pst1[(j0 + 2) * 64 + col] = (mij >> (k * 4 + 2)) & 1 ? e[2] : 0.f;
        Pst1[(j0 + 3) * 64 + col] = (mij >> (k * 4 + 3)) & 1 ? e[3] : 0.f;
        if (!diag) {
            float4 st;
            st.x = (mji >> (0 * 4 + k)) & 1 ? e[0] : 0.f;
            st.y = (mji >> (1 * 4 + k)) & 1 ? e[1] : 0.f;
            st.z = (mji >> (2 * 4 + k)) & 1 ? e[2] : 0.f;
            st.w = (mji >> (3 * 4 + k)) & 1 ? e[3] : 0.f;
            *(float4*)&Pst2[(i0 + k) * 64 + (j0 ^ swzB)] = st;
        }
    }
    __syncthreads();

    // ---- merged phase B: 8 fma chains, packed rowsums ----
    // acc1: O_i from Pst1 x njs (negated h_j)   acc2: O_j from Pst2 x his
    u64 acc1[4][2] = {}, acc2[4][2] = {};
    u64 rs1a = 0, rs1b = 0, rs2a = 0, rs2b = 0;
#pragma unroll 4
    for (int q = 0; q < 64; q++) {
        int swz = ((q >> 2) & 7) * 4;
        int po  = i0 ^ swz;
        int cf  = (((q >> 2) + tx) & 15) * 4;
        ulonglong2 p1 = *(const ulonglong2*)&Pst1[q * 64 + po];  // cols i0..i0+3
        ulonglong2 p2 = *(const ulonglong2*)&Pst2[q * 64 + po];  // cols i0..i0+3 (j-rows)
        ulonglong2 hn = *(const ulonglong2*)&njs[q * 64 + cf];   // -h[q][4tx..4tx+3]
        ulonglong2 hp = *(const ulonglong2*)&his[q * 64 + cf];   //  h[q][4tx..4tx+3]

        rs1a = f2add(rs1a, p1.x);  rs1b = f2add(rs1b, p1.y);
        rs2a = f2add(rs2a, p2.x);  rs2b = f2add(rs2b, p2.y);

        float f10, f11, f12, f13, f20, f21, f22, f23;
        unpack2(p1.x, f10, f11); unpack2(p1.y, f12, f13);
        unpack2(p2.x, f20, f21); unpack2(p2.y, f22, f23);
        u64 d10 = dupf(f10), d11 = dupf(f11), d12 = dupf(f12), d13 = dupf(f13);
        u64 d20 = dupf(f20), d21 = dupf(f21), d22 = dupf(f22), d23 = dupf(f23);

        acc1[0][0] = f2fma(d10, hn.x, acc1[0][0]);
        acc1[0][1] = f2fma(d10, hn.y, acc1[0][1]);
        acc1[1][0] = f2fma(d11, hn.x, acc1[1][0]);
        acc1[1][1] = f2fma(d11, hn.y, acc1[1][1]);
        acc1[2][0] = f2fma(d12, hn.x, acc1[2][0]);
        acc1[2][1] = f2fma(d12, hn.y, acc1[2][1]);
        acc1[3][0] = f2fma(d13, hn.x, acc1[3][0]);
        acc1[3][1] = f2fma(d13, hn.y, acc1[3][1]);

        acc2[0][0] = f2fma(d20, hp.x, acc2[0][0]);
        acc2[0][1] = f2fma(d20, hp.y, acc2[0][1]);
        acc2[1][0] = f2fma(d21, hp.x, acc2[1][0]);
        acc2[1][1] = f2fma(d21, hp.y, acc2[1][1]);
        acc2[2][0] = f2fma(d22, hp.x, acc2[2][0]);
        acc2[2][1] = f2fma(d22, hp.y, acc2[2][1]);
        acc2[3][0] = f2fma(d23, hp.x, acc2[3][0]);
        acc2[3][1] = f2fma(d23, hp.y, acc2[3][1]);
    }

    // ---- rowsums: all tx lanes identical -> tx==0 atomics only ----
    if (tx == 0) {
        float s0, s1, s2, s3;
        unpack2(rs1a, s0, s1); unpack2(rs1b, s2, s3);
        atomicAdd(&g_rowsum[gi0 + i0 + 0], s0);
        atomicAdd(&g_rowsum[gi0 + i0 + 1], s1);
        atomicAdd(&g_rowsum[gi0 + i0 + 2], s2);
        atomicAdd(&g_rowsum[gi0 + i0 + 3], s3);
        if (!diag) {
            unpack2(rs2a, s0, s1); unpack2(rs2b, s2, s3);
            atomicAdd(&g_rowsum[gj0 + i0 + 0], s0);
            atomicAdd(&g_rowsum[gj0 + i0 + 1], s1);
            atomicAdd(&g_rowsum[gj0 + i0 + 2], s2);
            atomicAdd(&g_rowsum[gj0 + i0 + 3], s3);
        }
    }

    // ---- epilogue: RED into g_o (acc1 negated: njs held -h) ----
#pragma unroll
    for (int k = 0; k < 4; k++) {
        float a0, a1, a2, a3;
        unpack2(acc1[k][0], a0, a1);
        unpack2(acc1[k][1], a2, a3);
        float* dst = &g_o[(size_t)(gi0 + i0 + k) * F + tx * 4];
        atomicAdd(dst + 0, -a0);
        atomicAdd(dst + 1, -a1);
        atomicAdd(dst + 2, -a2);
        atomicAdd(dst + 3, -a3);
    }
    if (!diag) {
#pragma unroll
        for (int k = 0; k < 4; k++) {
            float a0, a1, a2, a3;
            unpack2(acc2[k][0], a0, a1);
            unpack2(acc2[k][1], a2, a3);
            float* dst = &g_o[(size_t)(gj0 + i0 + k) * F + tx * 4];
            atomicAdd(dst + 0, a0);
            atomicAdd(dst + 1, a1);
            atomicAdd(dst + 2, a2);
            atomicAdd(dst + 3, a3);
        }
    }
}

// ---------------- K4: out = relu(g_o / rowsum) ------------------------------
__global__ __launch_bounds__(256) void k4_final(float* __restrict__ out) {
    int idx = blockIdx.x * 256 + threadIdx.x;          // thread per float
    float inv = 1.0f / g_rowsum[idx >> 6];
    out[idx] = fmaxf(g_o[idx] * inv, 0.f);
}

// ---------------- launch ---------------------------------------------------
extern "C" void kernel_launch(void* const* d_in, const int* in_sizes, int n_in,
                              void* d_out, int out_size) {
    const float* x   = (const float*)d_in[0];
    const int*   adj = (const int*)  d_in[1];
    const float* W   = (const float*)d_in[2];
    const float* a   = (const float*)d_in[3];
    float*       out = (float*)d_out;

    cudaFuncSetAttribute(k23_sym, cudaFuncAttributeMaxDynamicSharedMemorySize, K23S_SMEM);

    k1_gemm_h<<<128, 256>>>(x, W);
    k23_sym<<<NTRI, 256, K23S_SMEM>>>(adj, a);
    k4_final<<<N * F / 256, 256>>>(out);
}

// round 10
// speedup vs baseline: 1.1307x; 1.1307x over previous
#include <cuda_runtime.h>

#define N     2048
#define FIN   512
#define F     64
#define NT    32            // 64-row tiles per dimension
#define NTRI  528           // NT*(NT+1)/2

typedef unsigned long long u64;

// ---------------- scratch (static device allocations only) ----------------
__device__ float g_hpart[4][N * F];          // 2 MB: split-K partials of x@W
__device__ float g_h[N * F];                 // 512 KB
__device__ float g_rowsum[N];
__device__ float g_opart[NT][N * F];         // 16 MB: slot = other tile index

#define ABS2MASK 0x7FFFFFFF7FFFFFFFULL

__device__ __forceinline__ u64 f2add(u64 a, u64 b) {
    u64 r; asm("add.rn.f32x2 %0, %1, %2;" : "=l"(r) : "l"(a), "l"(b)); return r;
}
__device__ __forceinline__ u64 f2fma(u64 a, u64 b, u64 c) {
    u64 r; asm("fma.rn.f32x2 %0, %1, %2, %3;" : "=l"(r) : "l"(a), "l"(b), "l"(c)); return r;
}
__device__ __forceinline__ u64 dupf(float x) {
    u64 r; unsigned u = __float_as_uint(x);
    asm("mov.b64 %0, {%1,%1};" : "=l"(r) : "r"(u)); return r;
}
__device__ __forceinline__ float unpack_sum(u64 v) {
    float lo, hi;
    asm("mov.b64 {%0,%1}, %2;" : "=f"(lo), "=f"(hi) : "l"(v));
    return lo + hi;
}
__device__ __forceinline__ void unpack2(u64 v, float& lo, float& hi) {
    asm("mov.b64 {%0,%1}, %2;" : "=f"(lo), "=f"(hi) : "l"(v));
}

#define FMA4(a, s, v) { (a).x += (s)*(v).x; (a).y += (s)*(v).y; (a).z += (s)*(v).z; (a).w += (s)*(v).w; }

// ---------------- K1: split-K GEMM partials ---------------------------------
// grid (128 i-tiles, 4 k-splits); block = 16 rows x 64 f over K=128.
// 4 short stage/compute iterations; 512 blocks overlap latency chains.
__global__ __launch_bounds__(256) void k1_gemm_part(const float* __restrict__ x,
                                                    const float* __restrict__ W) {
    __shared__ float xs[16][128];   // 8 KB
    __shared__ float ws[32][F];     // 8 KB
    int tid = threadIdx.x;
    int r0 = blockIdx.x * 16;
    int ks = blockIdx.y;
    int kbase = ks * 128;

    // stage x tile [16][128]
#pragma unroll
    for (int u = 0; u < 2; u++) {
        int v = tid + u * 256;
        int r = v >> 5, c = v & 31;
        *(float4*)&xs[r][c * 4] =
            *(const float4*)&x[(size_t)(r0 + r) * FIN + kbase + c * 4];
    }

    int tx = tid & 15;
    int ty = tid >> 4;
    float4 acc[4];
#pragma unroll
    for (int q = 0; q < 4; q++) acc[q] = make_float4(0.f, 0.f, 0.f, 0.f);

#pragma unroll
    for (int kt = 0; kt < 128; kt += 32) {
        __syncthreads();
        // stage W tile [32][64]
#pragma unroll
        for (int u = 0; u < 2; u++) {
            int v = tid + u * 256;
            int r = v >> 4, c = v & 15;
            *(float4*)&ws[r][c * 4] =
                *(const float4*)&W[(size_t)(kbase + kt + r) * F + c * 4];
        }
        __syncthreads();
#pragma unroll
        for (int k4 = 0; k4 < 8; k4++) {
            float4 xv = *(const float4*)&xs[ty][kt + k4 * 4];
            float4 w0 = ((const float4*)&ws[k4 * 4 + 0][0])[tx];
            float4 w1 = ((const float4*)&ws[k4 * 4 + 1][0])[tx];
            float4 w2 = ((const float4*)&ws[k4 * 4 + 2][0])[tx];
            float4 w3 = ((const float4*)&ws[k4 * 4 + 3][0])[tx];
            FMA4(acc[0], xv.x, w0); FMA4(acc[1], xv.y, w1);
            FMA4(acc[2], xv.z, w2); FMA4(acc[3], xv.w, w3);
        }
    }
    float4 r;
    r.x = (acc[0].x + acc[1].x) + (acc[2].x + acc[3].x);
    r.y = (acc[0].y + acc[1].y) + (acc[2].y + acc[3].y);
    r.z = (acc[0].z + acc[1].z) + (acc[2].z + acc[3].z);
    r.w = (acc[0].w + acc[1].w) + (acc[2].w + acc[3].w);
    *(float4*)&g_hpart[ks][(size_t)(r0 + ty) * F + tx * 4] = r;
}

// ---------------- K1b: g_h = sum of 4 partials; zero rowsum ----------------
__global__ __launch_bounds__(256) void k1b_reduce() {
    int idx = blockIdx.x * 256 + threadIdx.x;   // 128 x 256 = 32768 float4s
    float4 a0 = ((const float4*)g_hpart[0])[idx];
    float4 a1 = ((const float4*)g_hpart[1])[idx];
    float4 a2 = ((const float4*)g_hpart[2])[idx];
    float4 a3 = ((const float4*)g_hpart[3])[idx];
    float4 r;
    r.x = (a0.x + a1.x) + (a2.x + a3.x);
    r.y = (a0.y + a1.y) + (a2.y + a3.y);
    r.z = (a0.z + a1.z) + (a2.z + a3.z);
    r.w = (a0.w + a1.w) + (a2.w + a3.w);
    ((float4*)g_h)[idx] = r;
    if (idx < N) g_rowsum[idx] = 0.0f;
}

// ---------------- K23sym: symmetric fused scores + exp + both AV products --
// Exact R7 structure (best measured): one block per upper-triangle tile pair,
// phase A E tile, split phase B1/B2, opart STG epilogues, occ 2.
#define K23S_SMEM ((4096 * 4 + 64) * 4)   // his, njs, Pst1, Pst2, a = 64.3KB

__global__ __launch_bounds__(256, 2) void k23_sym(const int* __restrict__ adj,
                                                  const float* __restrict__ a) {
    extern __shared__ float sm[];
    float* his  = sm;            // [64][64] rotated (i-tile h)
    float* njs  = sm + 4096;     // [64][64] rotated, negated (j-tile h)
    float* Pst1 = sm + 8192;     // [j][i] swizzled, mask adj[i,j]
    float* Pst2 = sm + 12288;    // [i][j] swizzled, mask adj[j,i]
    float* as_  = sm + 16384;    // [64]

    // triangular decode
    int t = blockIdx.x, ib = 0;
    while (t >= NT - ib) { t -= NT - ib; ib++; }
    int jb = ib + t;
    int gi0 = ib * 64, gj0 = jb * 64;
    bool diag = (ib == jb);

    int tid = threadIdx.x;
    int tx = tid & 15, ty = tid >> 4;
    int i0 = ty * 4, j0 = tx * 4;

    // ---- prefetch adjacency (both orientations), compress to bitmasks ----
    unsigned mij = 0, mji = 0;
#pragma unroll
    for (int k = 0; k < 4; k++) {
        int4 v = *(const int4*)&adj[(size_t)(gi0 + i0 + k) * N + gj0 + j0];
        unsigned b = (v.x > 0) | ((v.y > 0) << 1) | ((v.z > 0) << 2) | ((v.w > 0) << 3);
        mij |= b << (k * 4);     // bit (k*4+jj) = adj[gi0+i0+k][gj0+j0+jj]
    }
    if (!diag) {
#pragma unroll
        for (int jj = 0; jj < 4; jj++) {
            int4 v = *(const int4*)&adj[(size_t)(gj0 + j0 + jj) * N + gi0 + i0];
            unsigned b = (v.x > 0) | ((v.y > 0) << 1) | ((v.z > 0) << 2) | ((v.w > 0) << 3);
            mji |= b << (jj * 4);  // bit (jj*4+k) = adj[gj0+j0+jj][gi0+i0+k]
        }
    }

    // ---- stage his (rotated), njs (rotated + negated), a ----
    const float4* hgi = (const float4*)(g_h + (size_t)gi0 * F);
    const float4* hgj = (const float4*)(g_h + (size_t)gj0 * F);
#pragma unroll
    for (int u = 0; u < 4; u++) {
        int v = tid + u * 256;
        int r = v >> 4, c = v & 15;
        int cp = (c + (r >> 2)) & 15;
        *(float4*)&his[r * 64 + cp * 4] = hgi[v];
        float4 nv = hgj[v];
        nv.x = -nv.x; nv.y = -nv.y; nv.z = -nv.z; nv.w = -nv.w;
        *(float4*)&njs[r * 64 + cp * 4] = nv;
    }
    if (tid < 16) ((float4*)as_)[tid] = ((const float4*)a)[tid];
    __syncthreads();

    // ---- phase A: E tile, thread = 4i x 4j ----
    u64 accA[4][4] = {};
#pragma unroll
    for (int fc = 0; fc < 16; fc++) {
        ulonglong2 av = *(const ulonglong2*)&as_[fc * 4];
        int ci = ((fc + ty) & 15) * 4;
        int cj = ((fc + tx) & 15) * 4;
        ulonglong2 hr[4], nj[4];
#pragma unroll
        for (int k = 0; k < 4; k++) {
            hr[k] = *(const ulonglong2*)&his[(i0 + k) * 64 + ci];
            nj[k] = *(const ulonglong2*)&njs[(j0 + k) * 64 + cj];
        }
#pragma unroll
        for (int k = 0; k < 4; k++) {
#pragma unroll
            for (int jj = 0; jj < 4; jj++) {
                u64 d0 = f2add(hr[k].x, nj[jj].x) & ABS2MASK;
                accA[k][jj] = f2fma(d0, av.x, accA[k][jj]);
                u64 d1 = f2add(hr[k].y, nj[jj].y) & ABS2MASK;
                accA[k][jj] = f2fma(d1, av.y, accA[k][jj]);
            }
        }
    }

    // ---- exp once, mask twice, store Pst1 / Pst2 ----
    int swzA = (tx & 7) * 4;    // key for rows j0..j0+3  ((j>>2)&7 == tx&7)
    int swzB = (ty & 7) * 4;    // key for rows i0..i0+3
#pragma unroll
    for (int k = 0; k < 4; k++) {
        float e[4];
#pragma unroll
        for (int jj = 0; jj < 4; jj++)
            e[jj] = __expf(fmaxf(unpack_sum(accA[k][jj]), 0.f));
        int col = (i0 + k) ^ swzA;
        Pst1[(j0 + 0) * 64 + col] = (mij >> (k * 4 + 0)) & 1 ? e[0] : 0.f;
        Pst1[(j0 + 1) * 64 + col] = (mij >> (k * 4 + 1)) & 1 ? e[1] : 0.f;
        Pst1[(j0 + 2) * 64 + col] = (mij >> (k * 4 + 2)) & 1 ? e[2] : 0.f;
        Pst1[(j0 + 3) * 64 + col] = (mij >> (k * 4 + 3)) & 1 ? e[3] : 0.f;
        if (!diag) {
            float4 st;
            st.x = (mji >> (0 * 4 + k)) & 1 ? e[0] : 0.f;
            st.y = (mji >> (1 * 4 + k)) & 1 ? e[1] : 0.f;
            st.z = (mji >> (2 * 4 + k)) & 1 ? e[2] : 0.f;
            st.w = (mji >> (3 * 4 + k)) & 1 ? e[3] : 0.f;
            *(float4*)&Pst2[(i0 + k) * 64 + (j0 ^ swzB)] = st;
        }
    }
    __syncthreads();

    // ---- phase B1: accBi = sum_j P_ij * (-h_j)  -> O_i = -accBi ----
    {
        u64 accB[4][2] = {};
        float rsum[4] = {0.f, 0.f, 0.f, 0.f};
#pragma unroll 4
        for (int jq = 0; jq < 64; jq++) {
            int swz = ((jq >> 2) & 7) * 4;
            float4 p = *(const float4*)&Pst1[jq * 64 + (i0 ^ swz)];
            int cf = (((jq >> 2) + tx) & 15) * 4;
            ulonglong2 hv = *(const ulonglong2*)&njs[jq * 64 + cf];
            rsum[0] += p.x; rsum[1] += p.y; rsum[2] += p.z; rsum[3] += p.w;
            u64 p0 = dupf(p.x), p1 = dupf(p.y), p2 = dupf(p.z), p3 = dupf(p.w);
            accB[0][0] = f2fma(p0, hv.x, accB[0][0]);
            accB[0][1] = f2fma(p0, hv.y, accB[0][1]);
            accB[1][0] = f2fma(p1, hv.x, accB[1][0]);
            accB[1][1] = f2fma(p1, hv.y, accB[1][1]);
            accB[2][0] = f2fma(p2, hv.x, accB[2][0]);
            accB[2][1] = f2fma(p2, hv.y, accB[2][1]);
            accB[3][0] = f2fma(p3, hv.x, accB[3][0]);
            accB[3][1] = f2fma(p3, hv.y, accB[3][1]);
        }
        // all tx lanes hold identical rsum (same Pst1 reads) -> no reduction
        if (tx == 0)
#pragma unroll
            for (int k = 0; k < 4; k++)
                atomicAdd(&g_rowsum[gi0 + i0 + k], rsum[k]);
#pragma unroll
        for (int k = 0; k < 4; k++) {
            float a0, a1, a2, a3;
            unpack2(accB[k][0], a0, a1);
            unpack2(accB[k][1], a2, a3);
            *(float4*)&g_opart[jb][(size_t)(gi0 + i0 + k) * F + tx * 4] =
                make_float4(-a0, -a1, -a2, -a3);
        }
    }

    // ---- phase B2: accBj = sum_i P_ji * h_i  -> O_j ----
    if (!diag) {
        u64 accB[4][2] = {};
        float rsum[4] = {0.f, 0.f, 0.f, 0.f};
#pragma unroll 4
        for (int iq = 0; iq < 64; iq++) {
            int swz = ((iq >> 2) & 7) * 4;
            float4 p = *(const float4*)&Pst2[iq * 64 + (i0 ^ swz)];  // j-rows i0.. of jb block
            int cf = (((iq >> 2) + tx) & 15) * 4;
            ulonglong2 hv = *(const ulonglong2*)&his[iq * 64 + cf];
            rsum[0] += p.x; rsum[1] += p.y; rsum[2] += p.z; rsum[3] += p.w;
            u64 p0 = dupf(p.x), p1 = dupf(p.y), p2 = dupf(p.z), p3 = dupf(p.w);
            accB[0][0] = f2fma(p0, hv.x, accB[0][0]);
            accB[0][1] = f2fma(p0, hv.y, accB[0][1]);
            accB[1][0] = f2fma(p1, hv.x, accB[1][0]);
            accB[1][1] = f2fma(p1, hv.y, accB[1][1]);
            accB[2][0] = f2fma(p2, hv.x, accB[2][0]);
            accB[2][1] = f2fma(p2, hv.y, accB[2][1]);
            accB[3][0] = f2fma(p3, hv.x, accB[3][0]);
            accB[3][1] = f2fma(p3, hv.y, accB[3][1]);
        }
        // identical rsum across tx lanes -> no reduction
        if (tx == 0)
#pragma unroll
            for (int k = 0; k < 4; k++)
                atomicAdd(&g_rowsum[gj0 + i0 + k], rsum[k]);
#pragma unroll
        for (int k = 0; k < 4; k++) {
            float a0, a1, a2, a3;
            unpack2(accB[k][0], a0, a1);
            unpack2(accB[k][1], a2, a3);
            *(float4*)&g_opart[ib][(size_t)(gj0 + i0 + k) * F + tx * 4] =
                make_float4(a0, a1, a2, a3);
        }
    }
}

// ---------------- K4: out = relu((sum of 32 partials) / rowsum) ------------
__global__ __launch_bounds__(256) void k4_final(float* __restrict__ out) {
    int idx = blockIdx.x * 256 + threadIdx.x;          // 0 .. N*F-1
    float inv = 1.0f / g_rowsum[idx >> 6];
    float s = 0.f;
#pragma unroll
    for (int p = 0; p < NT; p++) s += g_opart[p][idx];
    out[idx] = fmaxf(s * inv, 0.f);
}

// ---------------- launch ---------------------------------------------------
extern "C" void kernel_launch(void* const* d_in, const int* in_sizes, int n_in,
                              void* d_out, int out_size) {
    const float* x   = (const float*)d_in[0];
    const int*   adj = (const int*)  d_in[1];
    const float* W   = (const float*)d_in[2];
    const float* a   = (const float*)d_in[3];
    float*       out = (float*)d_out;

    cudaFuncSetAttribute(k23_sym, cudaFuncAttributeMaxDynamicSharedMemorySize, K23S_SMEM);

    dim3 g1(128, 4);
    k1_gemm_part<<<g1, 256>>>(x, W);
    k1b_reduce<<<128, 256>>>();
    k23_sym<<<NTRI, 256, K23S_SMEM>>>(adj, a);
    k4_final<<<N * F / 256, 256>>>(out);
}

// round 11
// speedup vs baseline: 1.1515x; 1.0184x over previous
#include <cuda_runtime.h>

#define N     2048
#define FIN   512
#define F     64
#define NT    32            // 64-row tiles per dimension
#define NTRI  528           // NT*(NT+1)/2

typedef unsigned long long u64;

// ---------------- scratch (static device allocations only) ----------------
__device__ float g_hpart[4][N * F];          // 2 MB: split-K partials of x@W
__device__ float g_h[N * F];                 // 512 KB
__device__ float g_rowsum[N];
__device__ float g_opart[NT][N * F];         // 16 MB: slot = other tile index

#define ABS2MASK 0x7FFFFFFF7FFFFFFFULL

__device__ __forceinline__ u64 f2add(u64 a, u64 b) {
    u64 r; asm("add.rn.f32x2 %0, %1, %2;" : "=l"(r) : "l"(a), "l"(b)); return r;
}
__device__ __forceinline__ u64 f2fma(u64 a, u64 b, u64 c) {
    u64 r; asm("fma.rn.f32x2 %0, %1, %2, %3;" : "=l"(r) : "l"(a), "l"(b), "l"(c)); return r;
}
__device__ __forceinline__ u64 dupf(float x) {
    u64 r; unsigned u = __float_as_uint(x);
    asm("mov.b64 %0, {%1,%1};" : "=l"(r) : "r"(u)); return r;
}
__device__ __forceinline__ float unpack_sum(u64 v) {
    float lo, hi;
    asm("mov.b64 {%0,%1}, %2;" : "=f"(lo), "=f"(hi) : "l"(v));
    return lo + hi;
}
__device__ __forceinline__ void unpack2(u64 v, float& lo, float& hi) {
    asm("mov.b64 {%0,%1}, %2;" : "=f"(lo), "=f"(hi) : "l"(v));
}

#define FMA4(a, s, v) { (a).x += (s)*(v).x; (a).y += (s)*(v).y; (a).z += (s)*(v).z; (a).w += (s)*(v).w; }

// ---------------- K1: split-K GEMM partials ---------------------------------
__global__ __launch_bounds__(256) void k1_gemm_part(const float* __restrict__ x,
                                                    const float* __restrict__ W) {
    __shared__ float xs[16][128];   // 8 KB
    __shared__ float ws[32][F];     // 8 KB
    int tid = threadIdx.x;
    int r0 = blockIdx.x * 16;
    int ks = blockIdx.y;
    int kbase = ks * 128;

    // stage x tile [16][128]
#pragma unroll
    for (int u = 0; u < 2; u++) {
        int v = tid + u * 256;
        int r = v >> 5, c = v & 31;
        *(float4*)&xs[r][c * 4] =
            *(const float4*)&x[(size_t)(r0 + r) * FIN + kbase + c * 4];
    }

    int tx = tid & 15;
    int ty = tid >> 4;
    float4 acc[4];
#pragma unroll
    for (int q = 0; q < 4; q++) acc[q] = make_float4(0.f, 0.f, 0.f, 0.f);

#pragma unroll
    for (int kt = 0; kt < 128; kt += 32) {
        __syncthreads();
        // stage W tile [32][64]
#pragma unroll
        for (int u = 0; u < 2; u++) {
            int v = tid + u * 256;
            int r = v >> 4, c = v & 15;
            *(float4*)&ws[r][c * 4] =
                *(const float4*)&W[(size_t)(kbase + kt + r) * F + c * 4];
        }
        __syncthreads();
#pragma unroll
        for (int k4 = 0; k4 < 8; k4++) {
            float4 xv = *(const float4*)&xs[ty][kt + k4 * 4];
            float4 w0 = ((const float4*)&ws[k4 * 4 + 0][0])[tx];
            float4 w1 = ((const float4*)&ws[k4 * 4 + 1][0])[tx];
            float4 w2 = ((const float4*)&ws[k4 * 4 + 2][0])[tx];
            float4 w3 = ((const float4*)&ws[k4 * 4 + 3][0])[tx];
            FMA4(acc[0], xv.x, w0); FMA4(acc[1], xv.y, w1);
            FMA4(acc[2], xv.z, w2); FMA4(acc[3], xv.w, w3);
        }
    }
    float4 r;
    r.x = (acc[0].x + acc[1].x) + (acc[2].x + acc[3].x);
    r.y = (acc[0].y + acc[1].y) + (acc[2].y + acc[3].y);
    r.z = (acc[0].z + acc[1].z) + (acc[2].z + acc[3].z);
    r.w = (acc[0].w + acc[1].w) + (acc[2].w + acc[3].w);
    *(float4*)&g_hpart[ks][(size_t)(r0 + ty) * F + tx * 4] = r;
}

// ---------------- K1b: g_h = sum of 4 partials; zero rowsum ----------------
__global__ __launch_bounds__(256) void k1b_reduce() {
    int idx = blockIdx.x * 256 + threadIdx.x;   // 128 x 256 = 32768 float4s
    float4 a0 = ((const float4*)g_hpart[0])[idx];
    float4 a1 = ((const float4*)g_hpart[1])[idx];
    float4 a2 = ((const float4*)g_hpart[2])[idx];
    float4 a3 = ((const float4*)g_hpart[3])[idx];
    float4 r;
    r.x = (a0.x + a1.x) + (a2.x + a3.x);
    r.y = (a0.y + a1.y) + (a2.y + a3.y);
    r.z = (a0.z + a1.z) + (a2.z + a3.z);
    r.w = (a0.w + a1.w) + (a2.w + a3.w);
    ((float4*)g_h)[idx] = r;
    if (idx < N) g_rowsum[idx] = 0.0f;
}

// ---------------- K23sym: symmetric fused scores + exp + both AV products --
// Phase B flipped: acc[f][i-pair]; p consumed as loaded pairs (no p-dup),
// 4 h-dups/iter, rowsum via packed f2add. Same arithmetic order as R7.
#define K23S_SMEM ((4096 * 4 + 64) * 4)   // his, njs, Pst1, Pst2, a = 64.3KB

__global__ __launch_bounds__(256, 2) void k23_sym(const int* __restrict__ adj,
                                                  const float* __restrict__ a) {
    extern __shared__ float sm[];
    float* his  = sm;            // [64][64] rotated (i-tile h)
    float* njs  = sm + 4096;     // [64][64] rotated, negated (j-tile h)
    float* Pst1 = sm + 8192;     // [j][i] swizzled, mask adj[i,j]
    float* Pst2 = sm + 12288;    // [i][j] swizzled, mask adj[j,i]
    float* as_  = sm + 16384;    // [64]

    // triangular decode
    int t = blockIdx.x, ib = 0;
    while (t >= NT - ib) { t -= NT - ib; ib++; }
    int jb = ib + t;
    int gi0 = ib * 64, gj0 = jb * 64;
    bool diag = (ib == jb);

    int tid = threadIdx.x;
    int tx = tid & 15, ty = tid >> 4;
    int i0 = ty * 4, j0 = tx * 4;

    // ---- prefetch adjacency (both orientations), compress to bitmasks ----
    unsigned mij = 0, mji = 0;
#pragma unroll
    for (int k = 0; k < 4; k++) {
        int4 v = *(const int4*)&adj[(size_t)(gi0 + i0 + k) * N + gj0 + j0];
        unsigned b = (v.x > 0) | ((v.y > 0) << 1) | ((v.z > 0) << 2) | ((v.w > 0) << 3);
        mij |= b << (k * 4);     // bit (k*4+jj) = adj[gi0+i0+k][gj0+j0+jj]
    }
    if (!diag) {
#pragma unroll
        for (int jj = 0; jj < 4; jj++) {
            int4 v = *(const int4*)&adj[(size_t)(gj0 + j0 + jj) * N + gi0 + i0];
            unsigned b = (v.x > 0) | ((v.y > 0) << 1) | ((v.z > 0) << 2) | ((v.w > 0) << 3);
            mji |= b << (jj * 4);  // bit (jj*4+k) = adj[gj0+j0+jj][gi0+i0+k]
        }
    }

    // ---- stage his (rotated), njs (rotated + negated), a ----
    const float4* hgi = (const float4*)(g_h + (size_t)gi0 * F);
    const float4* hgj = (const float4*)(g_h + (size_t)gj0 * F);
#pragma unroll
    for (int u = 0; u < 4; u++) {
        int v = tid + u * 256;
        int r = v >> 4, c = v & 15;
        int cp = (c + (r >> 2)) & 15;
        *(float4*)&his[r * 64 + cp * 4] = hgi[v];
        float4 nv = hgj[v];
        nv.x = -nv.x; nv.y = -nv.y; nv.z = -nv.z; nv.w = -nv.w;
        *(float4*)&njs[r * 64 + cp * 4] = nv;
    }
    if (tid < 16) ((float4*)as_)[tid] = ((const float4*)a)[tid];
    __syncthreads();

    // ---- phase A: E tile, thread = 4i x 4j ----
    u64 accA[4][4] = {};
#pragma unroll
    for (int fc = 0; fc < 16; fc++) {
        ulonglong2 av = *(const ulonglong2*)&as_[fc * 4];
        int ci = ((fc + ty) & 15) * 4;
        int cj = ((fc + tx) & 15) * 4;
        ulonglong2 hr[4], nj[4];
#pragma unroll
        for (int k = 0; k < 4; k++) {
            hr[k] = *(const ulonglong2*)&his[(i0 + k) * 64 + ci];
            nj[k] = *(const ulonglong2*)&njs[(j0 + k) * 64 + cj];
        }
#pragma unroll
        for (int k = 0; k < 4; k++) {
#pragma unroll
            for (int jj = 0; jj < 4; jj++) {
                u64 d0 = f2add(hr[k].x, nj[jj].x) & ABS2MASK;
                accA[k][jj] = f2fma(d0, av.x, accA[k][jj]);
                u64 d1 = f2add(hr[k].y, nj[jj].y) & ABS2MASK;
                accA[k][jj] = f2fma(d1, av.y, accA[k][jj]);
            }
        }
    }

    // ---- exp once, mask twice, store Pst1 / Pst2 ----
    int swzA = (tx & 7) * 4;    // key for rows j0..j0+3  ((j>>2)&7 == tx&7)
    int swzB = (ty & 7) * 4;    // key for rows i0..i0+3
#pragma unroll
    for (int k = 0; k < 4; k++) {
        float e[4];
#pragma unroll
        for (int jj = 0; jj < 4; jj++)
            e[jj] = __expf(fmaxf(unpack_sum(accA[k][jj]), 0.f));
        int col = (i0 + k) ^ swzA;
        Pst1[(j0 + 0) * 64 + col] = (mij >> (k * 4 + 0)) & 1 ? e[0] : 0.f;
        Pst1[(j0 + 1) * 64 + col] = (mij >> (k * 4 + 1)) & 1 ? e[1] : 0.f;
        Pst1[(j0 + 2) * 64 + col] = (mij >> (k * 4 + 2)) & 1 ? e[2] : 0.f;
        Pst1[(j0 + 3) * 64 + col] = (mij >> (k * 4 + 3)) & 1 ? e[3] : 0.f;
        if (!diag) {
            float4 st;
            st.x = (mji >> (0 * 4 + k)) & 1 ? e[0] : 0.f;
            st.y = (mji >> (1 * 4 + k)) & 1 ? e[1] : 0.f;
            st.z = (mji >> (2 * 4 + k)) & 1 ? e[2] : 0.f;
            st.w = (mji >> (3 * 4 + k)) & 1 ? e[3] : 0.f;
            *(float4*)&Pst2[(i0 + k) * 64 + (j0 ^ swzB)] = st;
        }
    }
    __syncthreads();

    // ---- phase B1: O_i = sum_j P_ij * h_j (flipped: acc[f][i-pair]) ----
    {
        u64 acc[4][2] = {};          // [f][ipair]: lo=i0+2ip, hi=i0+2ip+1
        u64 rsa = 0, rsb = 0;        // packed rowsums (i0,i0+1), (i0+2,i0+3)
#pragma unroll 4
        for (int jq = 0; jq < 64; jq++) {
            int swz = ((jq >> 2) & 7) * 4;
            int cf = (((jq >> 2) + tx) & 15) * 4;
            ulonglong2 pp = *(const ulonglong2*)&Pst1[jq * 64 + (i0 ^ swz)];
            ulonglong2 hv = *(const ulonglong2*)&njs[jq * 64 + cf];
            rsa = f2add(rsa, pp.x);
            rsb = f2add(rsb, pp.y);
            float h0, h1, h2, h3;
            unpack2(hv.x, h0, h1); unpack2(hv.y, h2, h3);
            u64 H0 = dupf(h0), H1 = dupf(h1), H2 = dupf(h2), H3 = dupf(h3);
            acc[0][0] = f2fma(H0, pp.x, acc[0][0]);
            acc[0][1] = f2fma(H0, pp.y, acc[0][1]);
            acc[1][0] = f2fma(H1, pp.x, acc[1][0]);
            acc[1][1] = f2fma(H1, pp.y, acc[1][1]);
            acc[2][0] = f2fma(H2, pp.x, acc[2][0]);
            acc[2][1] = f2fma(H2, pp.y, acc[2][1]);
            acc[3][0] = f2fma(H3, pp.x, acc[3][0]);
            acc[3][1] = f2fma(H3, pp.y, acc[3][1]);
        }
        // identical rowsums across tx lanes -> tx==0 atomics only
        if (tx == 0) {
            float s0, s1, s2, s3;
            unpack2(rsa, s0, s1); unpack2(rsb, s2, s3);
            atomicAdd(&g_rowsum[gi0 + i0 + 0], s0);
            atomicAdd(&g_rowsum[gi0 + i0 + 1], s1);
            atomicAdd(&g_rowsum[gi0 + i0 + 2], s2);
            atomicAdd(&g_rowsum[gi0 + i0 + 3], s3);
        }
        // epilogue: gather transpose; njs held -h -> negate
        float v[4][4];   // [row r][f]
#pragma unroll
        for (int f = 0; f < 4; f++) {
            unpack2(acc[f][0], v[0][f], v[1][f]);
            unpack2(acc[f][1], v[2][f], v[3][f]);
        }
#pragma unroll
        for (int r = 0; r < 4; r++)
            *(float4*)&g_opart[jb][(size_t)(gi0 + i0 + r) * F + tx * 4] =
                make_float4(-v[r][0], -v[r][1], -v[r][2], -v[r][3]);
    }

    // ---- phase B2: O_j = sum_i P_ji * h_i ----
    if (!diag) {
        u64 acc[4][2] = {};
        u64 rsa = 0, rsb = 0;
#pragma unroll 4
        for (int iq = 0; iq < 64; iq++) {
            int swz = ((iq >> 2) & 7) * 4;
            int cf = (((iq >> 2) + tx) & 15) * 4;
            ulonglong2 pp = *(const ulonglong2*)&Pst2[iq * 64 + (i0 ^ swz)];
            ulonglong2 hv = *(const ulonglong2*)&his[iq * 64 + cf];
            rsa = f2add(rsa, pp.x);
            rsb = f2add(rsb, pp.y);
            float h0, h1, h2, h3;
            unpack2(hv.x, h0, h1); unpack2(hv.y, h2, h3);
            u64 H0 = dupf(h0), H1 = dupf(h1), H2 = dupf(h2), H3 = dupf(h3);
            acc[0][0] = f2fma(H0, pp.x, acc[0][0]);
            acc[0][1] = f2fma(H0, pp.y, acc[0][1]);
            acc[1][0] = f2fma(H1, pp.x, acc[1][0]);
            acc[1][1] = f2fma(H1, pp.y, acc[1][1]);
            acc[2][0] = f2fma(H2, pp.x, acc[2][0]);
            acc[2][1] = f2fma(H2, pp.y, acc[2][1]);
            acc[3][0] = f2fma(H3, pp.x, acc[3][0]);
            acc[3][1] = f2fma(H3, pp.y, acc[3][1]);
        }
        if (tx == 0) {
            float s0, s1, s2, s3;
            unpack2(rsa, s0, s1); unpack2(rsb, s2, s3);
            atomicAdd(&g_rowsum[gj0 + i0 + 0], s0);
            atomicAdd(&g_rowsum[gj0 + i0 + 1], s1);
            atomicAdd(&g_rowsum[gj0 + i0 + 2], s2);
            atomicAdd(&g_rowsum[gj0 + i0 + 3], s3);
        }
        float v[4][4];
#pragma unroll
        for (int f = 0; f < 4; f++) {
            unpack2(acc[f][0], v[0][f], v[1][f]);
            unpack2(acc[f][1], v[2][f], v[3][f]);
        }
#pragma unroll
        for (int r = 0; r < 4; r++)
            *(float4*)&g_opart[ib][(size_t)(gj0 + i0 + r) * F + tx * 4] =
                make_float4(v[r][0], v[r][1], v[r][2], v[r][3]);
    }
}

// ---------------- K4: out = relu((sum of 32 partials) / rowsum) ------------
// Thread per float; explicit 16-load batches -> MLP 16, L2 latency hidden.
__global__ __launch_bounds__(256) void k4_final(float* __restrict__ out) {
    int idx = blockIdx.x * 256 + threadIdx.x;          // 0 .. N*F-1
    float inv = 1.0f / g_rowsum[idx >> 6];
    float s0 = 0.f, s1 = 0.f, s2 = 0.f, s3 = 0.f;
#pragma unroll
    for (int b = 0; b < 2; b++) {
        float v[16];
#pragma unroll
        for (int p = 0; p < 16; p++) v[p] = g_opart[b * 16 + p][idx];
#pragma unroll
        for (int p = 0; p < 16; p += 4) {
            s0 += v[p + 0]; s1 += v[p + 1]; s2 += v[p + 2]; s3 += v[p + 3];
        }
    }
    out[idx] = fmaxf(((s0 + s1) + (s2 + s3)) * inv, 0.f);
}

// ---------------- launch ---------------------------------------------------
extern "C" void kernel_launch(void* const* d_in, const int* in_sizes, int n_in,
                              void* d_out, int out_size) {
    const float* x   = (const float*)d_in[0];
    const int*   adj = (const int*)  d_in[1];
    const float* W   = (const float*)d_in[2];
    const float* a   = (const float*)d_in[3];
    float*       out = (float*)d_out;

    cudaFuncSetAttribute(k23_sym, cudaFuncAttributeMaxDynamicSharedMemorySize, K23S_SMEM);

    dim3 g1(128, 4);
    k1_gemm_part<<<g1, 256>>>(x, W);
    k1b_reduce<<<128, 256>>>();
    k23_sym<<<NTRI, 256, K23S_SMEM>>>(adj, a);
    k4_final<<<N * F / 256, 256>>>(out);
}